// round 13
// baseline (speedup 1.0000x reference)
#include <cuda_runtime.h>
#include <cuda_bf16.h>
#include <math.h>

#define T  16
#define NN 20000
#define EE 320000
#define CC 128
#define HH 128
#define PP 100000
#define TN (T*NN)
#define TE (T*EE)

// ---------------- device scratch ----------------
__device__ float g_hs[TN*HH];
__device__ float g_layer[TN*HH];
__device__ float g_feats[TN*HH];
__device__ float g_gi[(size_t)TN*3*HH];
__device__ float g_gh[NN*3*HH];
__device__ float g_h[NN*HH];
__device__ float g_dinv[TN];
__device__ int   g_cnt[TN];
__device__ int   g_cursor[TN];
__device__ int   g_rowptr[T*(NN+1)];
__device__ int   g_col[TE];
__device__ __align__(16) unsigned int g_W1h[8704],  g_W1l[8704];
__device__ __align__(16) unsigned int g_W2h[8704],  g_W2l[8704];
__device__ __align__(16) unsigned int g_W3h[8704],  g_W3l[8704];
__device__ __align__(16) unsigned int g_wihh[26112], g_wihl[26112];
__device__ __align__(16) unsigned int g_whhh[26112], g_whhl[26112];

// ---------------- helpers ----------------
__device__ __forceinline__ unsigned int smem_u32(const void* p) {
    unsigned int a;
    asm("{ .reg .u64 t; cvta.to.shared.u64 t, %1; cvt.u32.u64 %0, t; }" : "=r"(a) : "l"(p));
    return a;
}
__device__ __forceinline__ void cp_async16(void* sp, const void* gp) {
    asm volatile("cp.async.cg.shared.global [%0], [%1], 16;"
                 :: "r"(smem_u32(sp)), "l"(gp) : "memory");
}
__device__ __forceinline__ void cp_commit() { asm volatile("cp.async.commit_group;" ::: "memory"); }
__device__ __forceinline__ void cp_wait0()  { asm volatile("cp.async.wait_group 0;" ::: "memory"); }

__device__ __forceinline__ void mma16816(float* c, const unsigned* a, const unsigned* b) {
    asm volatile("mma.sync.aligned.m16n8k16.row.col.f32.bf16.bf16.f32 "
                 "{%0,%1,%2,%3}, {%4,%5,%6,%7}, {%8,%9}, {%0,%1,%2,%3};"
                 : "+f"(c[0]), "+f"(c[1]), "+f"(c[2]), "+f"(c[3])
                 : "r"(a[0]), "r"(a[1]), "r"(a[2]), "r"(a[3]), "r"(b[0]), "r"(b[1]));
}
__device__ __forceinline__ void ldsm4(unsigned* r, unsigned addr) {
    asm volatile("ldmatrix.sync.aligned.m8n8.x4.shared.b16 {%0,%1,%2,%3}, [%4];"
                 : "=r"(r[0]), "=r"(r[1]), "=r"(r[2]), "=r"(r[3]) : "r"(addr));
}

// 3-term bf16 split mma over a 32(M)x32(N) warp tile, fragments via ldmatrix.
// A layout: [rows][68 words]; B layout: [n][68 words].  K=128 (8 k-steps).
__device__ __forceinline__ void mma_tile_ldsm(
    unsigned int baseAh, unsigned int baseAl,
    unsigned int baseBh, unsigned int baseBl,
    int lane, int warp_m, int warp_n, float acc[2][4][4])
{
    int m = lane >> 3, r = lane & 7;
    // A mats: [r0k0, r8k0, r0k8, r8k8] per 16-row im tile
    int aoff = ((warp_m*32 + (m & 1)*8 + r)*68 + (m >> 1)*4)*4;
    // B mats: [n(p)k0, n(p)k8, n(p+1)k0, n(p+1)k8] per n-pair
    int boff = ((warp_n*32 + (m >> 1)*8 + r)*68 + (m & 1)*4)*4;
    unsigned aAh0 = baseAh + aoff,               aAh1 = aAh0 + 16*68*4;
    unsigned aAl0 = baseAl + aoff,               aAl1 = aAl0 + 16*68*4;
    unsigned bBh0 = baseBh + boff,               bBh1 = bBh0 + 16*68*4;
    unsigned bBl0 = baseBl + boff,               bBl1 = bBl0 + 16*68*4;
    #pragma unroll
    for (int ks = 0; ks < 8; ks++) {
        unsigned ah[2][4], al[2][4], bh[2][4], bl[2][4];
        ldsm4(ah[0], aAh0); ldsm4(ah[1], aAh1);
        ldsm4(al[0], aAl0); ldsm4(al[1], aAl1);
        ldsm4(bh[0], bBh0); ldsm4(bh[1], bBh1);
        ldsm4(bl[0], bBl0); ldsm4(bl[1], bBl1);
        aAh0 += 32; aAh1 += 32; aAl0 += 32; aAl1 += 32;
        bBh0 += 32; bBh1 += 32; bBl0 += 32; bBl1 += 32;
        #pragma unroll
        for (int im = 0; im < 2; im++)
            #pragma unroll
            for (int in = 0; in < 4; in++)
                mma16816(acc[im][in], ah[im], &bh[in >> 1][(in & 1)*2]);
        #pragma unroll
        for (int im = 0; im < 2; im++)
            #pragma unroll
            for (int in = 0; in < 4; in++)
                mma16816(acc[im][in], ah[im], &bl[in >> 1][(in & 1)*2]);
        #pragma unroll
        for (int im = 0; im < 2; im++)
            #pragma unroll
            for (int in = 0; in < 4; in++)
                mma16816(acc[im][in], al[im], &bh[in >> 1][(in & 1)*2]);
    }
}

// ---------------- utility kernels ----------------
__global__ void zero_int_kernel(int* p, int n) {
    int i = blockIdx.x*blockDim.x + threadIdx.x;
    if (i < n) p[i] = 0;
}
__global__ void zero_float_kernel(float* p, int n) {
    int i = blockIdx.x*blockDim.x + threadIdx.x;
    if (i < n) p[i] = 0.0f;
}

__global__ void count_kernel(const int* __restrict__ ei, int* __restrict__ cnt) {
    int i = blockIdx.x*blockDim.x + threadIdx.x;
    if (i >= TE) return;
    int t = i / EE, e = i - t*EE;
    int dst = ei[(size_t)t*2*EE + EE + e];
    atomicAdd(&cnt[t*NN + dst], 1);
}

__global__ void dinv_kernel(const int* __restrict__ cnt, float* __restrict__ dinv) {
    int i = blockIdx.x*blockDim.x + threadIdx.x;
    if (i >= TN) return;
    dinv[i] = rsqrtf((float)cnt[i] + 1.0f);
}

__global__ void scan_kernel(const int* __restrict__ cnt, int* __restrict__ rowptr) {
    int t = blockIdx.x;
    const int* c = cnt + t*NN;
    int* rp = rowptr + t*(NN+1);
    __shared__ int wsum[32];
    int lane = threadIdx.x & 31;
    int wid  = threadIdx.x >> 5;
    int carry = 0;
    for (int base = 0; base < NN; base += 1024) {
        int i = base + threadIdx.x;
        int v = (i < NN) ? c[i] : 0;
        int inc = v;
        #pragma unroll
        for (int o = 1; o < 32; o <<= 1) {
            int y = __shfl_up_sync(0xffffffffu, inc, o);
            if (lane >= o) inc += y;
        }
        if (lane == 31) wsum[wid] = inc;
        __syncthreads();
        if (wid == 0) {
            int s = wsum[lane];
            #pragma unroll
            for (int o = 1; o < 32; o <<= 1) {
                int y = __shfl_up_sync(0xffffffffu, s, o);
                if (lane >= o) s += y;
            }
            wsum[lane] = s;
        }
        __syncthreads();
        int woff = wid ? wsum[wid-1] : 0;
        if (i < NN) rp[i] = carry + woff + inc - v;
        carry += wsum[31];
        __syncthreads();
    }
    if (threadIdx.x == 0) rp[NN] = carry;
}

__global__ void scatter_kernel(const int* __restrict__ ei, const int* __restrict__ rowptr,
                               int* __restrict__ cursor, int* __restrict__ col) {
    int i = blockIdx.x*blockDim.x + threadIdx.x;
    if (i >= TE) return;
    int t = i / EE, e = i - t*EE;
    int src = ei[(size_t)t*2*EE + e];
    int dst = ei[(size_t)t*2*EE + EE + e];
    int pos = rowptr[t*(NN+1) + dst] + atomicAdd(&cursor[t*NN + dst], 1);
    col[(size_t)t*EE + pos] = src;
}

// ---------------- weight image prep ----------------
__global__ void prep_weight_kernel(const float* __restrict__ W,
                                   unsigned int* __restrict__ img_h,
                                   unsigned int* __restrict__ img_l,
                                   int nout, int transposed) {
    int idx = blockIdx.x*blockDim.x + threadIdx.x;
    if (idx >= nout*64) return;
    int n = idx >> 6, kp = idx & 63, k0 = kp*2;
    float v0, v1;
    if (transposed) { v0 = W[k0*nout + n]; v1 = W[(k0+1)*nout + n]; }
    else            { v0 = W[n*128 + k0]; v1 = W[n*128 + k0 + 1]; }
    __nv_bfloat16 h0 = __float2bfloat16(v0), h1 = __float2bfloat16(v1);
    float r0 = v0 - __bfloat162float(h0), r1 = v1 - __bfloat162float(h1);
    __nv_bfloat16 l0 = __float2bfloat16(r0), l1 = __float2bfloat16(r1);
    int ct = n >> 7, nl = n & 127;
    int off = ct*8704 + nl*68 + kp;
    img_h[off] = (unsigned int)__bfloat16_as_ushort(h0)
               | ((unsigned int)__bfloat16_as_ushort(h1) << 16);
    img_l[off] = (unsigned int)__bfloat16_as_ushort(l0)
               | ((unsigned int)__bfloat16_as_ushort(l1) << 16);
}

// stage A rows (fp32 -> bf16 hi/lo) into [ROWS][68] padded smem
template<int NT, int ROWS>
__device__ __forceinline__ void stage_A(const float* __restrict__ A, int row0, int M,
                                        unsigned int* Ah, unsigned int* Al, int tid) {
    for (int u = tid; u < ROWS*16; u += NT) {
        int r = u >> 4, kq = u & 15;
        int grow = row0 + r;
        float4 va = make_float4(0.f,0.f,0.f,0.f), vb = va;
        if (grow < M) {
            va = *(const float4*)&A[(size_t)grow*128 + kq*8];
            vb = *(const float4*)&A[(size_t)grow*128 + kq*8 + 4];
        }
        float vals[8] = {va.x, va.y, va.z, va.w, vb.x, vb.y, vb.z, vb.w};
        unsigned int hi[4], lo[4];
        #pragma unroll
        for (int j = 0; j < 4; j++) {
            __nv_bfloat16 h0 = __float2bfloat16(vals[2*j]);
            __nv_bfloat16 h1 = __float2bfloat16(vals[2*j+1]);
            float r0 = vals[2*j]   - __bfloat162float(h0);
            float r1 = vals[2*j+1] - __bfloat162float(h1);
            __nv_bfloat16 l0 = __float2bfloat16(r0), l1 = __float2bfloat16(r1);
            hi[j] = (unsigned int)__bfloat16_as_ushort(h0)
                  | ((unsigned int)__bfloat16_as_ushort(h1) << 16);
            lo[j] = (unsigned int)__bfloat16_as_ushort(l0)
                  | ((unsigned int)__bfloat16_as_ushort(l1) << 16);
        }
        *(uint4*)&Ah[r*68 + kq*4] = make_uint4(hi[0], hi[1], hi[2], hi[3]);
        *(uint4*)&Al[r*68 + kq*4] = make_uint4(lo[0], lo[1], lo[2], lo[3]);
    }
}

// ---------------- HMMA bf16x3 GEMM (512 thr, double-buffered B via cp.async) ----------------
#define MM_SMEM (6*8704*4)

template<int EPI>  // 0: plain, 1: +bias[col], 2: *dinv[row]
__global__ void __launch_bounds__(512, 1) mgemm_kernel(
    const float* __restrict__ A,
    const unsigned int* __restrict__ Bimg_h, const unsigned int* __restrict__ Bimg_l,
    const float* __restrict__ bias, const float* __restrict__ dinv,
    float* __restrict__ out, int M, int ct_count, int ldOut)
{
    extern __shared__ unsigned int smem_u[];
    unsigned int* Ah = smem_u;
    unsigned int* Al = Ah + 8704;
    unsigned int* Bbuf = Al + 8704;     // 2 buffers x (Bh 8704 + Bl 8704)
    int tid  = threadIdx.x;
    int lane = tid & 31, w = tid >> 5;
    int warp_m = w & 3, warp_n = w >> 2;
    int g = lane >> 2, q = lane & 3;
    int row0 = blockIdx.x * 128;
    unsigned int baseAh = smem_u32(Ah), baseAl = smem_u32(Al);

    // prefetch ct=0 B into buffer 0 (overlaps A conversion)
    {
        const uint4* sh = (const uint4*)Bimg_h;
        const uint4* sl = (const uint4*)Bimg_l;
        uint4* dh = (uint4*)Bbuf;
        uint4* dl = dh + 2176;
        for (int i = tid; i < 2176; i += 512) {
            cp_async16(&dh[i], &sh[i]);
            cp_async16(&dl[i], &sl[i]);
        }
        cp_commit();
    }
    stage_A<512,128>(A, row0, M, Ah, Al, tid);
    cp_wait0();
    __syncthreads();

    for (int ct = 0; ct < ct_count; ct++) {
        const unsigned int* Bh = Bbuf + (ct & 1)*17408;
        const unsigned int* Bl = Bh + 8704;
        if (ct + 1 < ct_count) {
            const uint4* sh = (const uint4*)(Bimg_h + (ct+1)*8704);
            const uint4* sl = (const uint4*)(Bimg_l + (ct+1)*8704);
            uint4* dh = (uint4*)(Bbuf + ((ct+1) & 1)*17408);
            uint4* dl = dh + 2176;
            for (int i = tid; i < 2176; i += 512) {
                cp_async16(&dh[i], &sh[i]);
                cp_async16(&dl[i], &sl[i]);
            }
            cp_commit();
        }

        float acc[2][4][4];
        #pragma unroll
        for (int im = 0; im < 2; im++)
            #pragma unroll
            for (int in = 0; in < 4; in++)
                #pragma unroll
                for (int j = 0; j < 4; j++) acc[im][in][j] = 0.f;

        mma_tile_ldsm(baseAh, baseAl, smem_u32(Bh), smem_u32(Bl),
                      lane, warp_m, warp_n, acc);

        #pragma unroll
        for (int im = 0; im < 2; im++) {
            int row = row0 + warp_m*32 + im*16 + g;
            float s0 = 1.f, s1 = 1.f;
            if (EPI == 2) {
                s0 = (row < M)     ? dinv[row]   : 0.f;
                s1 = (row + 8 < M) ? dinv[row+8] : 0.f;
            }
            #pragma unroll
            for (int in = 0; in < 4; in++) {
                int col = warp_n*32 + in*8 + q*2;
                float2 bb = make_float2(0.f, 0.f);
                if (EPI == 1) bb = *(const float2*)&bias[ct*128 + col];
                float* op = out + (size_t)row*ldOut + ct*128 + col;
                if (row < M)
                    *(float2*)op = make_float2(acc[im][in][0]*s0 + bb.x,
                                               acc[im][in][1]*s0 + bb.y);
                if (row + 8 < M)
                    *(float2*)(op + (size_t)8*ldOut) =
                        make_float2(acc[im][in][2]*s1 + bb.x, acc[im][in][3]*s1 + bb.y);
            }
        }
        if (ct + 1 < ct_count) cp_wait0();
        __syncthreads();
    }
}

// ---------------- fused GRU step: TM=64, 256 thr, 2 blocks/SM, gates tail ----------------
#define GRU_SMEM (26112*4)

__global__ void __launch_bounds__(256, 2) gru_step_kernel(
    const float* __restrict__ gi,
    const unsigned int* __restrict__ Wh, const unsigned int* __restrict__ Wl,
    const float* __restrict__ bhh,
    float* __restrict__ h, float* __restrict__ gh)
{
    extern __shared__ unsigned int smem_u[];
    unsigned int* Ah = smem_u;           // [64][68]
    unsigned int* Al = Ah + 4352;
    unsigned int* Bh = Al + 4352;        // [128][68]
    unsigned int* Bl = Bh + 8704;
    int tid  = threadIdx.x;
    int lane = tid & 31, w = tid >> 5;   // 8 warps
    int warp_m = w & 1, warp_n = w >> 1; // 2(M) x 4(N), warp tile 32x32
    int g = lane >> 2, q = lane & 3;
    int row0 = blockIdx.x * 64;
    unsigned int baseAh = smem_u32(Ah), baseAl = smem_u32(Al);
    unsigned int baseBh = smem_u32(Bh), baseBl = smem_u32(Bl);

    // prefetch gate-0 B under A conversion
    {
        const uint4* sh = (const uint4*)Wh;
        const uint4* sl = (const uint4*)Wl;
        for (int i = tid; i < 2176; i += 256) {
            cp_async16(&((uint4*)Bh)[i], &sh[i]);
            cp_async16(&((uint4*)Bl)[i], &sl[i]);
        }
        cp_commit();
    }
    stage_A<256,64>(h, row0, NN, Ah, Al, tid);
    cp_wait0();
    __syncthreads();

    for (int gate = 0; gate < 3; gate++) {
        if (gate > 0) {
            const uint4* sh = (const uint4*)(Wh + gate*8704);
            const uint4* sl = (const uint4*)(Wl + gate*8704);
            for (int i = tid; i < 2176; i += 256) {
                ((uint4*)Bh)[i] = sh[i];
                ((uint4*)Bl)[i] = sl[i];
            }
            __syncthreads();
        }

        float acc[2][4][4];
        #pragma unroll
        for (int im = 0; im < 2; im++)
            #pragma unroll
            for (int in = 0; in < 4; in++)
                #pragma unroll
                for (int j = 0; j < 4; j++) acc[im][in][j] = 0.f;

        mma_tile_ldsm(baseAh, baseAl, baseBh, baseBl, lane, warp_m, warp_n, acc);

        // write gh (with b_hh) for this gate
        #pragma unroll
        for (int im = 0; im < 2; im++) {
            int row = row0 + warp_m*32 + im*16 + g;
            #pragma unroll
            for (int in = 0; in < 4; in++) {
                int col = warp_n*32 + in*8 + q*2;
                float2 bb = *(const float2*)&bhh[gate*128 + col];
                float* op = gh + (size_t)row*384 + gate*128 + col;
                if (row < NN)
                    *(float2*)op = make_float2(acc[im][in][0] + bb.x, acc[im][in][1] + bb.y);
                if (row + 8 < NN)
                    *(float2*)(op + (size_t)8*384) =
                        make_float2(acc[im][in][2] + bb.x, acc[im][in][3] + bb.y);
            }
        }
        __syncthreads();   // B reuse + gh visibility within block
    }

    // ---- gates tail: in-place h update for this block's 64 rows ----
    for (int idx = tid; idx < 64*32; idx += 256) {
        int nl = idx >> 5;
        int j4 = (idx & 31) * 4;
        int grow = row0 + nl;
        if (grow >= NN) break;
        const float* gir = gi + (size_t)grow*384;
        const float* ghr = gh + (size_t)grow*384;
        float4 ir  = *(const float4*)&gir[j4];
        float4 iz  = *(const float4*)&gir[128 + j4];
        float4 inn = *(const float4*)&gir[256 + j4];
        float4 hr  = *(const float4*)&ghr[j4];
        float4 hz  = *(const float4*)&ghr[128 + j4];
        float4 hn  = *(const float4*)&ghr[256 + j4];
        float4 hp  = *(const float4*)&h[(size_t)grow*128 + j4];
        float4 o;
        #define GATE(c) { \
            float rr = 1.f/(1.f+__expf(-(ir.c + hr.c))); \
            float zz = 1.f/(1.f+__expf(-(iz.c + hz.c))); \
            float nn2 = tanhf(inn.c + rr*hn.c); \
            o.c = (1.f - zz)*nn2 + zz*hp.c; }
        GATE(x) GATE(y) GATE(z) GATE(w)
        #undef GATE
        *(float4*)&h[(size_t)grow*128 + j4] = o;
    }
}

// ---------------- CSR gather aggregation ----------------
template<bool RELU, bool SCALED>
__global__ void agg_kernel(const float* __restrict__ hs, const float* __restrict__ dinv,
                           const int* __restrict__ rowptr, const int* __restrict__ col,
                           const float* __restrict__ bias, float* __restrict__ out)
{
    int g = blockIdx.x*blockDim.x + threadIdx.x;
    int w = g >> 5;
    if (w >= TN) return;
    int lane = g & 31;
    int t = w / NN, n = w - t*NN;
    const int* rp = rowptr + t*(NN+1);
    int beg = rp[n], end = rp[n+1];
    const int* cols = col + (size_t)t*EE;
    const float* hsf = hs + (size_t)t*NN*HH;
    const float* dvf = dinv + t*NN;
    int off = lane*4;
    float dv = dvf[n];
    float4 hn = *(const float4*)&hsf[n*HH + off];
    float4 acc;
    if (SCALED) acc = hn;
    else        acc = make_float4(hn.x*dv, hn.y*dv, hn.z*dv, hn.w*dv);
    int e = beg;
    for (; e + 4 <= end; e += 4) {
        int s0 = cols[e], s1 = cols[e+1], s2 = cols[e+2], s3 = cols[e+3];
        float4 v0 = *(const float4*)&hsf[s0*HH + off];
        float4 v1 = *(const float4*)&hsf[s1*HH + off];
        float4 v2 = *(const float4*)&hsf[s2*HH + off];
        float4 v3 = *(const float4*)&hsf[s3*HH + off];
        if (SCALED) {
            acc.x += (v0.x+v1.x)+(v2.x+v3.x);
            acc.y += (v0.y+v1.y)+(v2.y+v3.y);
            acc.z += (v0.z+v1.z)+(v2.z+v3.z);
            acc.w += (v0.w+v1.w)+(v2.w+v3.w);
        } else {
            float d0 = dvf[s0], d1 = dvf[s1], d2 = dvf[s2], d3 = dvf[s3];
            acc.x = fmaf(v0.x,d0, fmaf(v1.x,d1, fmaf(v2.x,d2, fmaf(v3.x,d3, acc.x))));
            acc.y = fmaf(v0.y,d0, fmaf(v1.y,d1, fmaf(v2.y,d2, fmaf(v3.y,d3, acc.y))));
            acc.z = fmaf(v0.z,d0, fmaf(v1.z,d1, fmaf(v2.z,d2, fmaf(v3.z,d3, acc.z))));
            acc.w = fmaf(v0.w,d0, fmaf(v1.w,d1, fmaf(v2.w,d2, fmaf(v3.w,d3, acc.w))));
        }
    }
    for (; e < end; e++) {
        int s = cols[e];
        float4 vv = *(const float4*)&hsf[s*HH + off];
        if (SCALED) {
            acc.x += vv.x; acc.y += vv.y; acc.z += vv.z; acc.w += vv.w;
        } else {
            float ds = dvf[s];
            acc.x = fmaf(vv.x, ds, acc.x); acc.y = fmaf(vv.y, ds, acc.y);
            acc.z = fmaf(vv.z, ds, acc.z); acc.w = fmaf(vv.w, ds, acc.w);
        }
    }
    float4 bb = *(const float4*)&bias[off];
    float4 o;
    o.x = fmaf(acc.x, dv, bb.x);
    o.y = fmaf(acc.y, dv, bb.y);
    o.z = fmaf(acc.z, dv, bb.z);
    o.w = fmaf(acc.w, dv, bb.w);
    if (RELU) {
        o.x = fmaxf(o.x, 0.f); o.y = fmaxf(o.y, 0.f);
        o.z = fmaxf(o.z, 0.f); o.w = fmaxf(o.w, 0.f);
    }
    *(float4*)&out[(size_t)w*HH + off] = o;
}

// ---------------- decode ----------------
__global__ void decode_kernel(const int* __restrict__ pairs, const float* __restrict__ h,
                              float* __restrict__ out)
{
    int g = blockIdx.x*blockDim.x + threadIdx.x;
    int w = g >> 5;
    if (w >= PP) return;
    int lane = g & 31;
    int s = pairs[w], d = pairs[PP + w];
    float4 a = *(const float4*)&h[(size_t)s*HH + lane*4];
    float4 b = *(const float4*)&h[(size_t)d*HH + lane*4];
    float sum = a.x*b.x + a.y*b.y + a.z*b.z + a.w*b.w;
    #pragma unroll
    for (int o = 16; o; o >>= 1) sum += __shfl_xor_sync(0xffffffffu, sum, o);
    if (lane == 0) out[w] = sum;
}

// ---------------- launch ----------------
extern "C" void kernel_launch(void* const* d_in, const int* in_sizes, int n_in,
                              void* d_out, int out_size)
{
    const float* x_seq = (const float*)d_in[0];
    const int*   ei    = (const int*)d_in[1];
    const int*   pairs = (const int*)d_in[2];
    const float* W1 = (const float*)d_in[3];
    const float* b1 = (const float*)d_in[4];
    const float* W2 = (const float*)d_in[5];
    const float* b2 = (const float*)d_in[6];
    const float* W3 = (const float*)d_in[7];
    const float* b3 = (const float*)d_in[8];
    const float* w_ih = (const float*)d_in[9];
    const float* w_hh = (const float*)d_in[10];
    const float* b_ih = (const float*)d_in[11];
    const float* b_hh = (const float*)d_in[12];
    float* out = (float*)d_out;
    (void)in_sizes; (void)n_in; (void)out_size;

    void* p;
    float *hs, *layer, *feats, *gi, *gh, *h, *dinv;
    int *cnt, *cursor, *rowptr, *col;
    unsigned int *W1h,*W1l,*W2h,*W2l,*W3h,*W3l,*wihh,*wihl,*whhh,*whhl;
    cudaGetSymbolAddress(&p, g_hs);     hs     = (float*)p;
    cudaGetSymbolAddress(&p, g_layer);  layer  = (float*)p;
    cudaGetSymbolAddress(&p, g_feats);  feats  = (float*)p;
    cudaGetSymbolAddress(&p, g_gi);     gi     = (float*)p;
    cudaGetSymbolAddress(&p, g_gh);     gh     = (float*)p;
    cudaGetSymbolAddress(&p, g_h);      h      = (float*)p;
    cudaGetSymbolAddress(&p, g_dinv);   dinv   = (float*)p;
    cudaGetSymbolAddress(&p, g_cnt);    cnt    = (int*)p;
    cudaGetSymbolAddress(&p, g_cursor); cursor = (int*)p;
    cudaGetSymbolAddress(&p, g_rowptr); rowptr = (int*)p;
    cudaGetSymbolAddress(&p, g_col);    col    = (int*)p;
    cudaGetSymbolAddress(&p, g_W1h);  W1h  = (unsigned int*)p;
    cudaGetSymbolAddress(&p, g_W1l);  W1l  = (unsigned int*)p;
    cudaGetSymbolAddress(&p, g_W2h);  W2h  = (unsigned int*)p;
    cudaGetSymbolAddress(&p, g_W2l);  W2l  = (unsigned int*)p;
    cudaGetSymbolAddress(&p, g_W3h);  W3h  = (unsigned int*)p;
    cudaGetSymbolAddress(&p, g_W3l);  W3l  = (unsigned int*)p;
    cudaGetSymbolAddress(&p, g_wihh); wihh = (unsigned int*)p;
    cudaGetSymbolAddress(&p, g_wihl); wihl = (unsigned int*)p;
    cudaGetSymbolAddress(&p, g_whhh); whhh = (unsigned int*)p;
    cudaGetSymbolAddress(&p, g_whhl); whhl = (unsigned int*)p;

    cudaFuncSetAttribute(mgemm_kernel<0>, cudaFuncAttributeMaxDynamicSharedMemorySize, MM_SMEM);
    cudaFuncSetAttribute(mgemm_kernel<1>, cudaFuncAttributeMaxDynamicSharedMemorySize, MM_SMEM);
    cudaFuncSetAttribute(mgemm_kernel<2>, cudaFuncAttributeMaxDynamicSharedMemorySize, MM_SMEM);
    cudaFuncSetAttribute(gru_step_kernel, cudaFuncAttributeMaxDynamicSharedMemorySize, GRU_SMEM);

    // idx 0..2
    prep_weight_kernel<<<(128*64+255)/256, 256>>>(W1, W1h, W1l, 128, 1);
    zero_int_kernel<<<(TN+255)/256, 256>>>(cnt, TN);
    zero_int_kernel<<<(TN+255)/256, 256>>>(cursor, TN);

    // idx 3: first big GEMM (ncu profiling window)
    mgemm_kernel<0><<<TN/128, 512, MM_SMEM>>>(x_seq, W1h, W1l, nullptr, nullptr, hs, TN, 1, 128);

    // remaining preps + CSR build
    zero_float_kernel<<<(NN*HH+255)/256, 256>>>(h, NN*HH);
    prep_weight_kernel<<<(128*64+255)/256, 256>>>(W2, W2h, W2l, 128, 1);
    prep_weight_kernel<<<(128*64+255)/256, 256>>>(W3, W3h, W3l, 128, 1);
    prep_weight_kernel<<<(384*64+255)/256, 256>>>(w_ih, wihh, wihl, 384, 0);
    prep_weight_kernel<<<(384*64+255)/256, 256>>>(w_hh, whhh, whhl, 384, 0);
    count_kernel<<<(TE+255)/256, 256>>>(ei, cnt);
    dinv_kernel<<<(TN+255)/256, 256>>>(cnt, dinv);
    scan_kernel<<<T, 1024>>>(cnt, rowptr);
    scatter_kernel<<<(TE+255)/256, 256>>>(ei, rowptr, cursor, col);

    // GCN layers (layer1: raw hs + per-edge dinv; layers 2-3: dinv folded into epilogue)
    int aggBlocks = (TN*32 + 255)/256;
    agg_kernel<true,false><<<aggBlocks, 256>>>(hs, dinv, rowptr, col, b1, layer);
    mgemm_kernel<2><<<TN/128, 512, MM_SMEM>>>(layer, W2h, W2l, nullptr, dinv, hs, TN, 1, 128);
    agg_kernel<true,true ><<<aggBlocks, 256>>>(hs, dinv, rowptr, col, b2, layer);
    mgemm_kernel<2><<<TN/128, 512, MM_SMEM>>>(layer, W3h, W3l, nullptr, dinv, hs, TN, 1, 128);
    agg_kernel<false,true><<<aggBlocks, 256>>>(hs, dinv, rowptr, col, b3, feats);

    // GRU: batched input gates, then 16 fused steps
    mgemm_kernel<1><<<TN/128, 512, MM_SMEM>>>(feats, wihh, wihl, b_ih, nullptr, gi, TN, 3, 384);

    int gruBlocks = (NN + 63)/64;
    for (int t = 0; t < T; t++)
        gru_step_kernel<<<gruBlocks, 256, GRU_SMEM>>>(gi + (size_t)t*NN*3*HH, whhh, whhl, b_hh, h, gh);

    decode_kernel<<<(PP*32 + 255)/256, 256>>>(pairs, h, out);
}

// round 16
// speedup vs baseline: 1.0455x; 1.0455x over previous
#include <cuda_runtime.h>
#include <cuda_bf16.h>
#include <math.h>

#define T  16
#define NN 20000
#define EE 320000
#define CC 128
#define HH 128
#define PP 100000
#define TN (T*NN)
#define TE (T*EE)

// ---------------- device scratch ----------------
__device__ float g_hs[TN*HH];
__device__ float g_layer[TN*HH];
__device__ float g_feats[TN*HH];
__device__ float g_gi[(size_t)TN*3*HH];
__device__ float g_gh[NN*3*HH];
__device__ float g_h[NN*HH];
__device__ float g_dinv[TN];
__device__ int   g_cnt[TN];
__device__ int   g_cursor[TN];
__device__ int   g_rowptr[T*(NN+1)];
__device__ int   g_col[TE];
__device__ __align__(16) unsigned int g_W1h[8704],  g_W1l[8704];
__device__ __align__(16) unsigned int g_W2h[8704],  g_W2l[8704];
__device__ __align__(16) unsigned int g_W3h[8704],  g_W3l[8704];
__device__ __align__(16) unsigned int g_wihh[26112], g_wihl[26112];
__device__ __align__(16) unsigned int g_whhh[26112], g_whhl[26112];

// ---------------- helpers ----------------
__device__ __forceinline__ unsigned int smem_u32(const void* p) {
    unsigned int a;
    asm("{ .reg .u64 t; cvta.to.shared.u64 t, %1; cvt.u32.u64 %0, t; }" : "=r"(a) : "l"(p));
    return a;
}
__device__ __forceinline__ void cp_async16(void* sp, const void* gp) {
    asm volatile("cp.async.cg.shared.global [%0], [%1], 16;"
                 :: "r"(smem_u32(sp)), "l"(gp) : "memory");
}
__device__ __forceinline__ void cp_commit() { asm volatile("cp.async.commit_group;" ::: "memory"); }
__device__ __forceinline__ void cp_wait0()  { asm volatile("cp.async.wait_group 0;" ::: "memory"); }

__device__ __forceinline__ void mma16816(float* c, const unsigned* a, const unsigned* b) {
    asm volatile("mma.sync.aligned.m16n8k16.row.col.f32.bf16.bf16.f32 "
                 "{%0,%1,%2,%3}, {%4,%5,%6,%7}, {%8,%9}, {%0,%1,%2,%3};"
                 : "+f"(c[0]), "+f"(c[1]), "+f"(c[2]), "+f"(c[3])
                 : "r"(a[0]), "r"(a[1]), "r"(a[2]), "r"(a[3]), "r"(b[0]), "r"(b[1]));
}

// 3-term bf16 split mma over a 32(M)x32(N) warp tile, scalar LDS fragments.
// A layout: [rows][68 words]; B layout: [n][68 words].  K=128 (8 k-steps).
__device__ __forceinline__ void mma_tile32(
    const unsigned int* Ah, const unsigned int* Al,
    const unsigned int* Bh, const unsigned int* Bl,
    int warp_m, int warp_n, int g, int q, float acc[2][4][4])
{
    const unsigned int* Abh = Ah + (warp_m*32 + g)*68 + q;
    const unsigned int* Abl = Al + (warp_m*32 + g)*68 + q;
    const unsigned int* Bbh = Bh + (warp_n*32 + g)*68 + q;
    const unsigned int* Bbl = Bl + (warp_n*32 + g)*68 + q;
    #pragma unroll
    for (int ks = 0; ks < 8; ks++) {
        int ko = ks*8;
        unsigned int ah[2][4], al[2][4], bh[4][2], bl[4][2];
        #pragma unroll
        for (int im = 0; im < 2; im++) {
            int ro = im*1088;
            ah[im][0] = Abh[ro + ko];
            ah[im][1] = Abh[ro + 544 + ko];
            ah[im][2] = Abh[ro + ko + 4];
            ah[im][3] = Abh[ro + 544 + ko + 4];
            al[im][0] = Abl[ro + ko];
            al[im][1] = Abl[ro + 544 + ko];
            al[im][2] = Abl[ro + ko + 4];
            al[im][3] = Abl[ro + 544 + ko + 4];
        }
        #pragma unroll
        for (int in = 0; in < 4; in++) {
            int no = in*544;
            bh[in][0] = Bbh[no + ko];
            bh[in][1] = Bbh[no + ko + 4];
            bl[in][0] = Bbl[no + ko];
            bl[in][1] = Bbl[no + ko + 4];
        }
        #pragma unroll
        for (int im = 0; im < 2; im++)
            #pragma unroll
            for (int in = 0; in < 4; in++)
                mma16816(acc[im][in], ah[im], bh[in]);
        #pragma unroll
        for (int im = 0; im < 2; im++)
            #pragma unroll
            for (int in = 0; in < 4; in++)
                mma16816(acc[im][in], ah[im], bl[in]);
        #pragma unroll
        for (int im = 0; im < 2; im++)
            #pragma unroll
            for (int in = 0; in < 4; in++)
                mma16816(acc[im][in], al[im], bh[in]);
    }
}

// ---------------- utility kernels ----------------
__global__ void zero_int_kernel(int* p, int n) {
    int i = blockIdx.x*blockDim.x + threadIdx.x;
    if (i < n) p[i] = 0;
}
__global__ void zero_float_kernel(float* p, int n) {
    int i = blockIdx.x*blockDim.x + threadIdx.x;
    if (i < n) p[i] = 0.0f;
}

__global__ void count_kernel(const int* __restrict__ ei, int* __restrict__ cnt) {
    int i = blockIdx.x*blockDim.x + threadIdx.x;
    if (i >= TE) return;
    int t = i / EE, e = i - t*EE;
    int dst = ei[(size_t)t*2*EE + EE + e];
    atomicAdd(&cnt[t*NN + dst], 1);
}

__global__ void dinv_kernel(const int* __restrict__ cnt, float* __restrict__ dinv) {
    int i = blockIdx.x*blockDim.x + threadIdx.x;
    if (i >= TN) return;
    dinv[i] = rsqrtf((float)cnt[i] + 1.0f);
}

__global__ void scan_kernel(const int* __restrict__ cnt, int* __restrict__ rowptr) {
    int t = blockIdx.x;
    const int* c = cnt + t*NN;
    int* rp = rowptr + t*(NN+1);
    __shared__ int wsum[32];
    int lane = threadIdx.x & 31;
    int wid  = threadIdx.x >> 5;
    int carry = 0;
    for (int base = 0; base < NN; base += 1024) {
        int i = base + threadIdx.x;
        int v = (i < NN) ? c[i] : 0;
        int inc = v;
        #pragma unroll
        for (int o = 1; o < 32; o <<= 1) {
            int y = __shfl_up_sync(0xffffffffu, inc, o);
            if (lane >= o) inc += y;
        }
        if (lane == 31) wsum[wid] = inc;
        __syncthreads();
        if (wid == 0) {
            int s = wsum[lane];
            #pragma unroll
            for (int o = 1; o < 32; o <<= 1) {
                int y = __shfl_up_sync(0xffffffffu, s, o);
                if (lane >= o) s += y;
            }
            wsum[lane] = s;
        }
        __syncthreads();
        int woff = wid ? wsum[wid-1] : 0;
        if (i < NN) rp[i] = carry + woff + inc - v;
        carry += wsum[31];
        __syncthreads();
    }
    if (threadIdx.x == 0) rp[NN] = carry;
}

__global__ void scatter_kernel(const int* __restrict__ ei, const int* __restrict__ rowptr,
                               int* __restrict__ cursor, int* __restrict__ col) {
    int i = blockIdx.x*blockDim.x + threadIdx.x;
    if (i >= TE) return;
    int t = i / EE, e = i - t*EE;
    int src = ei[(size_t)t*2*EE + e];
    int dst = ei[(size_t)t*2*EE + EE + e];
    int pos = rowptr[t*(NN+1) + dst] + atomicAdd(&cursor[t*NN + dst], 1);
    col[(size_t)t*EE + pos] = src;
}

// ---------------- weight image prep ----------------
__global__ void prep_weight_kernel(const float* __restrict__ W,
                                   unsigned int* __restrict__ img_h,
                                   unsigned int* __restrict__ img_l,
                                   int nout, int transposed) {
    int idx = blockIdx.x*blockDim.x + threadIdx.x;
    if (idx >= nout*64) return;
    int n = idx >> 6, kp = idx & 63, k0 = kp*2;
    float v0, v1;
    if (transposed) { v0 = W[k0*nout + n]; v1 = W[(k0+1)*nout + n]; }
    else            { v0 = W[n*128 + k0]; v1 = W[n*128 + k0 + 1]; }
    __nv_bfloat16 h0 = __float2bfloat16(v0), h1 = __float2bfloat16(v1);
    float r0 = v0 - __bfloat162float(h0), r1 = v1 - __bfloat162float(h1);
    __nv_bfloat16 l0 = __float2bfloat16(r0), l1 = __float2bfloat16(r1);
    int ct = n >> 7, nl = n & 127;
    int off = ct*8704 + nl*68 + kp;
    img_h[off] = (unsigned int)__bfloat16_as_ushort(h0)
               | ((unsigned int)__bfloat16_as_ushort(h1) << 16);
    img_l[off] = (unsigned int)__bfloat16_as_ushort(l0)
               | ((unsigned int)__bfloat16_as_ushort(l1) << 16);
}

// stage A rows (fp32 -> bf16 hi/lo) into [64][68] padded smem
__device__ __forceinline__ void stage_A64(const float* __restrict__ A, int row0, int M,
                                          unsigned int* Ah, unsigned int* Al, int tid) {
    for (int u = tid; u < 1024; u += 256) {
        int r = u >> 4, kq = u & 15;
        int grow = row0 + r;
        float4 va = make_float4(0.f,0.f,0.f,0.f), vb = va;
        if (grow < M) {
            va = *(const float4*)&A[(size_t)grow*128 + kq*8];
            vb = *(const float4*)&A[(size_t)grow*128 + kq*8 + 4];
        }
        float vals[8] = {va.x, va.y, va.z, va.w, vb.x, vb.y, vb.z, vb.w};
        unsigned int hi[4], lo[4];
        #pragma unroll
        for (int j = 0; j < 4; j++) {
            __nv_bfloat16 h0 = __float2bfloat16(vals[2*j]);
            __nv_bfloat16 h1 = __float2bfloat16(vals[2*j+1]);
            float r0 = vals[2*j]   - __bfloat162float(h0);
            float r1 = vals[2*j+1] - __bfloat162float(h1);
            __nv_bfloat16 l0 = __float2bfloat16(r0), l1 = __float2bfloat16(r1);
            hi[j] = (unsigned int)__bfloat16_as_ushort(h0)
                  | ((unsigned int)__bfloat16_as_ushort(h1) << 16);
            lo[j] = (unsigned int)__bfloat16_as_ushort(l0)
                  | ((unsigned int)__bfloat16_as_ushort(l1) << 16);
        }
        *(uint4*)&Ah[r*68 + kq*4] = make_uint4(hi[0], hi[1], hi[2], hi[3]);
        *(uint4*)&Al[r*68 + kq*4] = make_uint4(lo[0], lo[1], lo[2], lo[3]);
    }
}

// ---------------- HMMA bf16x3 GEMM: 64-row tile, 256 thr, 2 blocks/SM ----------------
#define MM_SMEM (26112*4)   // Ah/Al [64][68] + Bh/Bl [128][68] = 104448 B

template<int EPI>  // 0: plain, 1: +bias[col], 2: *dinv[row]
__global__ void __launch_bounds__(256, 2) mgemm_kernel(
    const float* __restrict__ A,
    const unsigned int* __restrict__ Bimg_h, const unsigned int* __restrict__ Bimg_l,
    const float* __restrict__ bias, const float* __restrict__ dinv,
    float* __restrict__ out, int M, int ct_count, int ldOut)
{
    extern __shared__ unsigned int smem_u[];
    unsigned int* Ah = smem_u;           // [64][68]
    unsigned int* Al = Ah + 4352;
    unsigned int* Bh = Al + 4352;        // [128][68]
    unsigned int* Bl = Bh + 8704;
    int tid  = threadIdx.x;
    int lane = tid & 31, w = tid >> 5;   // 8 warps
    int warp_m = w & 1, warp_n = w >> 1; // 2(M) x 4(N)
    int g = lane >> 2, q = lane & 3;
    int row0 = blockIdx.x * 64;

    // prefetch ct=0 B under A conversion
    {
        const uint4* sh = (const uint4*)Bimg_h;
        const uint4* sl = (const uint4*)Bimg_l;
        for (int i = tid; i < 2176; i += 256) {
            cp_async16(&((uint4*)Bh)[i], &sh[i]);
            cp_async16(&((uint4*)Bl)[i], &sl[i]);
        }
        cp_commit();
    }
    stage_A64(A, row0, M, Ah, Al, tid);
    cp_wait0();
    __syncthreads();

    for (int ct = 0; ct < ct_count; ct++) {
        if (ct > 0) {
            const uint4* sh = (const uint4*)(Bimg_h + ct*8704);
            const uint4* sl = (const uint4*)(Bimg_l + ct*8704);
            for (int i = tid; i < 2176; i += 256) {
                ((uint4*)Bh)[i] = sh[i];
                ((uint4*)Bl)[i] = sl[i];
            }
            __syncthreads();
        }

        float acc[2][4][4];
        #pragma unroll
        for (int im = 0; im < 2; im++)
            #pragma unroll
            for (int in = 0; in < 4; in++)
                #pragma unroll
                for (int j = 0; j < 4; j++) acc[im][in][j] = 0.f;

        mma_tile32(Ah, Al, Bh, Bl, warp_m, warp_n, g, q, acc);

        #pragma unroll
        for (int im = 0; im < 2; im++) {
            int row = row0 + warp_m*32 + im*16 + g;
            float s0 = 1.f, s1 = 1.f;
            if (EPI == 2) {
                s0 = (row < M)     ? dinv[row]   : 0.f;
                s1 = (row + 8 < M) ? dinv[row+8] : 0.f;
            }
            #pragma unroll
            for (int in = 0; in < 4; in++) {
                int col = warp_n*32 + in*8 + q*2;
                float2 bb = make_float2(0.f, 0.f);
                if (EPI == 1) bb = *(const float2*)&bias[ct*128 + col];
                float* op = out + (size_t)row*ldOut + ct*128 + col;
                if (row < M)
                    *(float2*)op = make_float2(acc[im][in][0]*s0 + bb.x,
                                               acc[im][in][1]*s0 + bb.y);
                if (row + 8 < M)
                    *(float2*)(op + (size_t)8*ldOut) =
                        make_float2(acc[im][in][2]*s1 + bb.x, acc[im][in][3]*s1 + bb.y);
            }
        }
        if (ct + 1 < ct_count) __syncthreads();
    }
}

// ---------------- fused GRU step: TM=64, 256 thr, 2 blocks/SM, gates tail ----------------
#define GRU_SMEM (26112*4)

__global__ void __launch_bounds__(256, 2) gru_step_kernel(
    const float* __restrict__ gi,
    const unsigned int* __restrict__ Wh, const unsigned int* __restrict__ Wl,
    const float* __restrict__ bhh,
    float* __restrict__ h, float* __restrict__ gh)
{
    extern __shared__ unsigned int smem_u[];
    unsigned int* Ah = smem_u;           // [64][68]
    unsigned int* Al = Ah + 4352;
    unsigned int* Bh = Al + 4352;        // [128][68]
    unsigned int* Bl = Bh + 8704;
    int tid  = threadIdx.x;
    int lane = tid & 31, w = tid >> 5;   // 8 warps
    int warp_m = w & 1, warp_n = w >> 1; // 2(M) x 4(N)
    int g = lane >> 2, q = lane & 3;
    int row0 = blockIdx.x * 64;

    // prefetch gate-0 B under A conversion
    {
        const uint4* sh = (const uint4*)Wh;
        const uint4* sl = (const uint4*)Wl;
        for (int i = tid; i < 2176; i += 256) {
            cp_async16(&((uint4*)Bh)[i], &sh[i]);
            cp_async16(&((uint4*)Bl)[i], &sl[i]);
        }
        cp_commit();
    }
    stage_A64(h, row0, NN, Ah, Al, tid);
    cp_wait0();
    __syncthreads();

    for (int gate = 0; gate < 3; gate++) {
        if (gate > 0) {
            const uint4* sh = (const uint4*)(Wh + gate*8704);
            const uint4* sl = (const uint4*)(Wl + gate*8704);
            for (int i = tid; i < 2176; i += 256) {
                ((uint4*)Bh)[i] = sh[i];
                ((uint4*)Bl)[i] = sl[i];
            }
            __syncthreads();
        }

        float acc[2][4][4];
        #pragma unroll
        for (int im = 0; im < 2; im++)
            #pragma unroll
            for (int in = 0; in < 4; in++)
                #pragma unroll
                for (int j = 0; j < 4; j++) acc[im][in][j] = 0.f;

        mma_tile32(Ah, Al, Bh, Bl, warp_m, warp_n, g, q, acc);

        // write gh (with b_hh) for this gate
        #pragma unroll
        for (int im = 0; im < 2; im++) {
            int row = row0 + warp_m*32 + im*16 + g;
            #pragma unroll
            for (int in = 0; in < 4; in++) {
                int col = warp_n*32 + in*8 + q*2;
                float2 bb = *(const float2*)&bhh[gate*128 + col];
                float* op = gh + (size_t)row*384 + gate*128 + col;
                if (row < NN)
                    *(float2*)op = make_float2(acc[im][in][0] + bb.x, acc[im][in][1] + bb.y);
                if (row + 8 < NN)
                    *(float2*)(op + (size_t)8*384) =
                        make_float2(acc[im][in][2] + bb.x, acc[im][in][3] + bb.y);
            }
        }
        __syncthreads();   // B reuse + gh visibility within block
    }

    // ---- gates tail: in-place h update for this block's 64 rows ----
    for (int idx = tid; idx < 64*32; idx += 256) {
        int nl = idx >> 5;
        int j4 = (idx & 31) * 4;
        int grow = row0 + nl;
        if (grow >= NN) break;
        const float* gir = gi + (size_t)grow*384;
        const float* ghr = gh + (size_t)grow*384;
        float4 ir  = *(const float4*)&gir[j4];
        float4 iz  = *(const float4*)&gir[128 + j4];
        float4 inn = *(const float4*)&gir[256 + j4];
        float4 hr  = *(const float4*)&ghr[j4];
        float4 hz  = *(const float4*)&ghr[128 + j4];
        float4 hn  = *(const float4*)&ghr[256 + j4];
        float4 hp  = *(const float4*)&h[(size_t)grow*128 + j4];
        float4 o;
        #define GATE(c) { \
            float rr = 1.f/(1.f+__expf(-(ir.c + hr.c))); \
            float zz = 1.f/(1.f+__expf(-(iz.c + hz.c))); \
            float nn2 = tanhf(inn.c + rr*hn.c); \
            o.c = (1.f - zz)*nn2 + zz*hp.c; }
        GATE(x) GATE(y) GATE(z) GATE(w)
        #undef GATE
        *(float4*)&h[(size_t)grow*128 + j4] = o;
    }
}

// ---------------- CSR gather aggregation ----------------
template<bool RELU, bool SCALED>
__global__ void agg_kernel(const float* __restrict__ hs, const float* __restrict__ dinv,
                           const int* __restrict__ rowptr, const int* __restrict__ col,
                           const float* __restrict__ bias, float* __restrict__ out)
{
    int g = blockIdx.x*blockDim.x + threadIdx.x;
    int w = g >> 5;
    if (w >= TN) return;
    int lane = g & 31;
    int t = w / NN, n = w - t*NN;
    const int* rp = rowptr + t*(NN+1);
    int beg = rp[n], end = rp[n+1];
    const int* cols = col + (size_t)t*EE;
    const float* hsf = hs + (size_t)t*NN*HH;
    const float* dvf = dinv + t*NN;
    int off = lane*4;
    float dv = dvf[n];
    float4 hn = *(const float4*)&hsf[n*HH + off];
    float4 acc;
    if (SCALED) acc = hn;
    else        acc = make_float4(hn.x*dv, hn.y*dv, hn.z*dv, hn.w*dv);
    int e = beg;
    for (; e + 4 <= end; e += 4) {
        int s0 = cols[e], s1 = cols[e+1], s2 = cols[e+2], s3 = cols[e+3];
        float4 v0 = *(const float4*)&hsf[s0*HH + off];
        float4 v1 = *(const float4*)&hsf[s1*HH + off];
        float4 v2 = *(const float4*)&hsf[s2*HH + off];
        float4 v3 = *(const float4*)&hsf[s3*HH + off];
        if (SCALED) {
            acc.x += (v0.x+v1.x)+(v2.x+v3.x);
            acc.y += (v0.y+v1.y)+(v2.y+v3.y);
            acc.z += (v0.z+v1.z)+(v2.z+v3.z);
            acc.w += (v0.w+v1.w)+(v2.w+v3.w);
        } else {
            float d0 = dvf[s0], d1 = dvf[s1], d2 = dvf[s2], d3 = dvf[s3];
            acc.x = fmaf(v0.x,d0, fmaf(v1.x,d1, fmaf(v2.x,d2, fmaf(v3.x,d3, acc.x))));
            acc.y = fmaf(v0.y,d0, fmaf(v1.y,d1, fmaf(v2.y,d2, fmaf(v3.y,d3, acc.y))));
            acc.z = fmaf(v0.z,d0, fmaf(v1.z,d1, fmaf(v2.z,d2, fmaf(v3.z,d3, acc.z))));
            acc.w = fmaf(v0.w,d0, fmaf(v1.w,d1, fmaf(v2.w,d2, fmaf(v3.w,d3, acc.w))));
        }
    }
    for (; e < end; e++) {
        int s = cols[e];
        float4 vv = *(const float4*)&hsf[s*HH + off];
        if (SCALED) {
            acc.x += vv.x; acc.y += vv.y; acc.z += vv.z; acc.w += vv.w;
        } else {
            float ds = dvf[s];
            acc.x = fmaf(vv.x, ds, acc.x); acc.y = fmaf(vv.y, ds, acc.y);
            acc.z = fmaf(vv.z, ds, acc.z); acc.w = fmaf(vv.w, ds, acc.w);
        }
    }
    float4 bb = *(const float4*)&bias[off];
    float4 o;
    o.x = fmaf(acc.x, dv, bb.x);
    o.y = fmaf(acc.y, dv, bb.y);
    o.z = fmaf(acc.z, dv, bb.z);
    o.w = fmaf(acc.w, dv, bb.w);
    if (RELU) {
        o.x = fmaxf(o.x, 0.f); o.y = fmaxf(o.y, 0.f);
        o.z = fmaxf(o.z, 0.f); o.w = fmaxf(o.w, 0.f);
    }
    *(float4*)&out[(size_t)w*HH + off] = o;
}

// ---------------- decode ----------------
__global__ void decode_kernel(const int* __restrict__ pairs, const float* __restrict__ h,
                              float* __restrict__ out)
{
    int g = blockIdx.x*blockDim.x + threadIdx.x;
    int w = g >> 5;
    if (w >= PP) return;
    int lane = g & 31;
    int s = pairs[w], d = pairs[PP + w];
    float4 a = *(const float4*)&h[(size_t)s*HH + lane*4];
    float4 b = *(const float4*)&h[(size_t)d*HH + lane*4];
    float sum = a.x*b.x + a.y*b.y + a.z*b.z + a.w*b.w;
    #pragma unroll
    for (int o = 16; o; o >>= 1) sum += __shfl_xor_sync(0xffffffffu, sum, o);
    if (lane == 0) out[w] = sum;
}

// ---------------- launch ----------------
extern "C" void kernel_launch(void* const* d_in, const int* in_sizes, int n_in,
                              void* d_out, int out_size)
{
    const float* x_seq = (const float*)d_in[0];
    const int*   ei    = (const int*)d_in[1];
    const int*   pairs = (const int*)d_in[2];
    const float* W1 = (const float*)d_in[3];
    const float* b1 = (const float*)d_in[4];
    const float* W2 = (const float*)d_in[5];
    const float* b2 = (const float*)d_in[6];
    const float* W3 = (const float*)d_in[7];
    const float* b3 = (const float*)d_in[8];
    const float* w_ih = (const float*)d_in[9];
    const float* w_hh = (const float*)d_in[10];
    const float* b_ih = (const float*)d_in[11];
    const float* b_hh = (const float*)d_in[12];
    float* out = (float*)d_out;
    (void)in_sizes; (void)n_in; (void)out_size;

    void* p;
    float *hs, *layer, *feats, *gi, *gh, *h, *dinv;
    int *cnt, *cursor, *rowptr, *col;
    unsigned int *W1h,*W1l,*W2h,*W2l,*W3h,*W3l,*wihh,*wihl,*whhh,*whhl;
    cudaGetSymbolAddress(&p, g_hs);     hs     = (float*)p;
    cudaGetSymbolAddress(&p, g_layer);  layer  = (float*)p;
    cudaGetSymbolAddress(&p, g_feats);  feats  = (float*)p;
    cudaGetSymbolAddress(&p, g_gi);     gi     = (float*)p;
    cudaGetSymbolAddress(&p, g_gh);     gh     = (float*)p;
    cudaGetSymbolAddress(&p, g_h);      h      = (float*)p;
    cudaGetSymbolAddress(&p, g_dinv);   dinv   = (float*)p;
    cudaGetSymbolAddress(&p, g_cnt);    cnt    = (int*)p;
    cudaGetSymbolAddress(&p, g_cursor); cursor = (int*)p;
    cudaGetSymbolAddress(&p, g_rowptr); rowptr = (int*)p;
    cudaGetSymbolAddress(&p, g_col);    col    = (int*)p;
    cudaGetSymbolAddress(&p, g_W1h);  W1h  = (unsigned int*)p;
    cudaGetSymbolAddress(&p, g_W1l);  W1l  = (unsigned int*)p;
    cudaGetSymbolAddress(&p, g_W2h);  W2h  = (unsigned int*)p;
    cudaGetSymbolAddress(&p, g_W2l);  W2l  = (unsigned int*)p;
    cudaGetSymbolAddress(&p, g_W3h);  W3h  = (unsigned int*)p;
    cudaGetSymbolAddress(&p, g_W3l);  W3l  = (unsigned int*)p;
    cudaGetSymbolAddress(&p, g_wihh); wihh = (unsigned int*)p;
    cudaGetSymbolAddress(&p, g_wihl); wihl = (unsigned int*)p;
    cudaGetSymbolAddress(&p, g_whhh); whhh = (unsigned int*)p;
    cudaGetSymbolAddress(&p, g_whhl); whhl = (unsigned int*)p;

    cudaFuncSetAttribute(mgemm_kernel<0>, cudaFuncAttributeMaxDynamicSharedMemorySize, MM_SMEM);
    cudaFuncSetAttribute(mgemm_kernel<1>, cudaFuncAttributeMaxDynamicSharedMemorySize, MM_SMEM);
    cudaFuncSetAttribute(mgemm_kernel<2>, cudaFuncAttributeMaxDynamicSharedMemorySize, MM_SMEM);
    cudaFuncSetAttribute(gru_step_kernel, cudaFuncAttributeMaxDynamicSharedMemorySize, GRU_SMEM);

    // idx 0..2
    prep_weight_kernel<<<(128*64+255)/256, 256>>>(W1, W1h, W1l, 128, 1);
    zero_int_kernel<<<(TN+255)/256, 256>>>(cnt, TN);
    zero_int_kernel<<<(TN+255)/256, 256>>>(cursor, TN);

    // idx 3: first big GEMM (ncu profiling window)
    mgemm_kernel<0><<<TN/64, 256, MM_SMEM>>>(x_seq, W1h, W1l, nullptr, nullptr, hs, TN, 1, 128);

    // remaining preps + CSR build
    zero_float_kernel<<<(NN*HH+255)/256, 256>>>(h, NN*HH);
    prep_weight_kernel<<<(128*64+255)/256, 256>>>(W2, W2h, W2l, 128, 1);
    prep_weight_kernel<<<(128*64+255)/256, 256>>>(W3, W3h, W3l, 128, 1);
    prep_weight_kernel<<<(384*64+255)/256, 256>>>(w_ih, wihh, wihl, 384, 0);
    prep_weight_kernel<<<(384*64+255)/256, 256>>>(w_hh, whhh, whhl, 384, 0);
    count_kernel<<<(TE+255)/256, 256>>>(ei, cnt);
    dinv_kernel<<<(TN+255)/256, 256>>>(cnt, dinv);
    scan_kernel<<<T, 1024>>>(cnt, rowptr);
    scatter_kernel<<<(TE+255)/256, 256>>>(ei, rowptr, cursor, col);

    // GCN layers (layer1: raw hs + per-edge dinv; layers 2-3: dinv folded into epilogue)
    int aggBlocks = (TN*32 + 255)/256;
    agg_kernel<true,false><<<aggBlocks, 256>>>(hs, dinv, rowptr, col, b1, layer);
    mgemm_kernel<2><<<TN/64, 256, MM_SMEM>>>(layer, W2h, W2l, nullptr, dinv, hs, TN, 1, 128);
    agg_kernel<true,true ><<<aggBlocks, 256>>>(hs, dinv, rowptr, col, b2, layer);
    mgemm_kernel<2><<<TN/64, 256, MM_SMEM>>>(layer, W3h, W3l, nullptr, dinv, hs, TN, 1, 128);
    agg_kernel<false,true><<<aggBlocks, 256>>>(hs, dinv, rowptr, col, b3, feats);

    // GRU: batched input gates, then 16 fused steps
    mgemm_kernel<1><<<TN/64, 256, MM_SMEM>>>(feats, wihh, wihl, b_ih, nullptr, gi, TN, 3, 384);

    int gruBlocks = (NN + 63)/64;
    for (int t = 0; t < T; t++)
        gru_step_kernel<<<gruBlocks, 256, GRU_SMEM>>>(gi + (size_t)t*NN*3*HH, whhh, whhl, b_hh, h, gh);

    decode_kernel<<<(PP*32 + 255)/256, 256>>>(pairs, h, out);
}